// round 6
// baseline (speedup 1.0000x reference)
#include <cuda_runtime.h>
#include <cuda_fp16.h>
#include <cstdint>

#define E_EDGES 50000
#define MTILE   64
#define MTILES  782                     // ceil(50000/64)
#define EPAD    (MTILES * MTILE)        // 50048
#define KFLAT   8192                    // 128 (c) * 64 (i)
#define BK      64
#define NT      128                     // k-tiles; tile t <-> channel c = t

// scratch
__device__ float  g_P [(size_t)EPAD * 512];    // [e][i(64)][kk(8)] fp32
__device__ float  g_mT[(size_t)EPAD * 1024];   // [e][c(128)][kk(8)] fp32
__device__ __half g_Whi[(size_t)128 * KFLAT];  // [o][k], k = c*64+i
__device__ __half g_Wlo[(size_t)128 * KFLAT];

// ---------------- helpers ----------------
__device__ __forceinline__ uint32_t smem_u32(const void* p) {
    uint32_t a;
    asm("{ .reg .u64 t; cvta.to.shared.u64 t, %1; cvt.u32.u64 %0, t; }" : "=r"(a) : "l"(p));
    return a;
}
#define SWZ128(x) ((x) ^ (((x) >> 3) & 0x70))

__device__ __forceinline__ void cp16(uint32_t dst, const void* src) {
    asm volatile("cp.async.cg.shared.global [%0], [%1], 16;" :: "r"(dst), "l"(src));
}
#define CP_COMMIT() asm volatile("cp.async.commit_group;" ::: "memory")
#define CP_WAIT(n)  asm volatile("cp.async.wait_group %0;" :: "n"(n) : "memory")

__device__ __forceinline__ void ldmx4(uint32_t* d, uint32_t addr) {
    asm volatile("ldmatrix.sync.aligned.m8n8.x4.shared.b16 {%0,%1,%2,%3}, [%4];"
        : "=r"(d[0]), "=r"(d[1]), "=r"(d[2]), "=r"(d[3]) : "r"(addr));
}
__device__ __forceinline__ void mma16816(float* c, const uint32_t* a, const uint32_t* b) {
    asm volatile(
        "mma.sync.aligned.m16n8k16.row.col.f32.f16.f16.f32 "
        "{%0,%1,%2,%3}, {%4,%5,%6,%7}, {%8,%9}, {%0,%1,%2,%3};"
        : "+f"(c[0]), "+f"(c[1]), "+f"(c[2]), "+f"(c[3])
        : "r"(a[0]), "r"(a[1]), "r"(a[2]), "r"(a[3]), "r"(b[0]), "r"(b[1]));
}
__device__ __forceinline__ unsigned pack_hh(__half a, __half b) {
    __half2 t = __halves2half2(a, b);
    return *reinterpret_cast<unsigned*>(&t);
}
__device__ __forceinline__ unsigned pack_ff(float a, float b) {
    __half2 t = __floats2half2_rn(a, b);
    return *reinterpret_cast<unsigned*>(&t);
}

// ---------------------------------------------------------------------------
// Kernel 0: W split + transpose (fp16 hi/lo).  g_Whi/lo[o][c*64+i] = W[c,i,o].
// ---------------------------------------------------------------------------
__global__ void __launch_bounds__(256) wsplit_kernel(const float* __restrict__ W) {
    const int c = blockIdx.x;
    const int tid = threadIdx.x;
    __shared__ __align__(16) float sW[64 * 128];   // [i][o]
    #pragma unroll
    for (int l = 0; l < 8; l++)
        ((float4*)sW)[tid + 256 * l] = ((const float4*)(W + (size_t)c * 8192))[tid + 256 * l];
    __syncthreads();

    const int o  = tid >> 1;
    const int i0 = (tid & 1) * 32;
    size_t base = (size_t)o * KFLAT + c * 64 + i0;
    #pragma unroll
    for (int g = 0; g < 4; g++) {
        __half h[8]; float r[8];
        #pragma unroll
        for (int j = 0; j < 8; j++) {
            float a = sW[(i0 + g * 8 + j) * 128 + o];
            h[j] = __float2half_rn(a);
            r[j] = a - __half2float(h[j]);
        }
        uint4 vh = make_uint4(pack_hh(h[0],h[1]), pack_hh(h[2],h[3]), pack_hh(h[4],h[5]), pack_hh(h[6],h[7]));
        uint4 vl = make_uint4(pack_ff(r[0],r[1]), pack_ff(r[2],r[3]), pack_ff(r[4],r[5]), pack_ff(r[6],r[7]));
        *(uint4*)&g_Whi[base + g * 8] = vh;
        *(uint4*)&g_Wlo[base + g * 8] = vl;
    }
}

// ---------------------------------------------------------------------------
// Kernel 1: per-edge precompute of P = rbf @ sph[:, :8]  (fp32) and
// mT[e][c][kk] = m[e*8+kk][c]  (fp32 transpose for fast per-tile access).
// ---------------------------------------------------------------------------
__global__ void __launch_bounds__(256) prep_kernel(
    const float* __restrict__ rbf,   // (E, 64, 16)
    const float* __restrict__ sph,   // (E, 16, 16)
    const float* __restrict__ m)     // (E*8, 128)
{
    const int e   = blockIdx.x;
    const int tid = threadIdx.x;

    if (e >= E_EDGES) {
        *(float2*)&g_P[(size_t)e * 512 + tid * 2] = make_float2(0.f, 0.f);
        ((float4*)(g_mT + (size_t)e * 1024))[tid] = make_float4(0.f, 0.f, 0.f, 0.f);
        return;
    }

    __shared__ __align__(16) float s_rbf[1024];   // [i][s]
    __shared__ __align__(16) float s_sph[128];    // [s][kk]
    __shared__ __align__(16) float s_m[1024];     // [kk][c]
    __shared__ __align__(16) float s_P[512];      // [i][kk]

    ((float4*)s_rbf)[tid] = ((const float4*)(rbf + (size_t)e * 1024))[tid];
    ((float4*)s_m)[tid]   = ((const float4*)(m   + (size_t)e * 1024))[tid];
    if (tid < 128) {
        int s = tid >> 3, kk = tid & 7;
        s_sph[tid] = sph[(size_t)e * 256 + s * 16 + kk];
    }
    __syncthreads();

    #pragma unroll
    for (int rq = 0; rq < 2; rq++) {
        int o = tid + 256 * rq;
        int i = o >> 3, kk = o & 7;
        float acc = 0.f;
        #pragma unroll
        for (int s = 0; s < 16; s++)
            acc += s_rbf[i * 16 + s] * s_sph[s * 8 + kk];
        s_P[o] = acc;
    }
    __syncthreads();

    // store P coalesced
    *(float2*)&g_P[(size_t)e * 512 + tid * 2] = make_float2(s_P[tid * 2], s_P[tid * 2 + 1]);

    // store mT: thread owns (c = tid>>1, kk half)
    const int c  = tid >> 1;
    const int hf = (tid & 1) * 4;
    float4 v = make_float4(s_m[(hf + 0) * 128 + c], s_m[(hf + 1) * 128 + c],
                           s_m[(hf + 2) * 128 + c], s_m[(hf + 3) * 128 + c]);
    *(float4*)&g_mT[(size_t)e * 1024 + c * 8 + hf] = v;
}

// ---------------------------------------------------------------------------
// Kernel 2: fused A-production + HMMA GEMM.
//   CTA = 64 edges x 128 outputs.  P resident in smem (fp32, 128KB).
//   Per k-tile t (= channel c): compute A[e][i] = sum_kk P[e,i,kk]*mT[e,t,kk]
//   on the fma pipe, split fp16 hi/lo, STS; mma.sync 3 passes on tensor pipe.
// ---------------------------------------------------------------------------
#define OFF_P 0
#define OFF_A 131072            // 2 stages x (hi 8192 + lo 8192)
#define OFF_B 163840            // 2 stages x (hi 16384 + lo 16384)
#define SMEM_TOTAL_GEMM 229376

__global__ void __launch_bounds__(256, 1) gemm_kernel(float* __restrict__ out) {
    extern __shared__ char smem[];
    const uint32_t sbase = smem_u32(smem);
    const int tid  = threadIdx.x;
    const int wid  = tid >> 5, lane = tid & 31;
    const int warp_m = wid >> 2;        // 0..1 -> 32-row slab
    const int warp_n = wid & 3;         // 0..3 -> 32-col slab
    const int e0 = blockIdx.x * MTILE;

    // ---- B stage loader: row rr (0..127), 64B half hh ----
    const int rr = tid >> 1;
    const int hh = (tid & 1) * 64;
    const char* pBhi = (const char*)g_Whi + (size_t)rr * (KFLAT * 2) + hh;
    const char* pBlo = (const char*)g_Wlo + (size_t)rr * (KFLAT * 2) + hh;
    uint32_t bswz[4];
    #pragma unroll
    for (int q = 0; q < 4; q++) bswz[q] = SWZ128(rr * 128 + hh + q * 16);

    auto loadB = [&](int t, int buf) {
        const uint32_t bu = sbase + OFF_B + buf * 32768;
        const size_t ko = (size_t)t * 128;
        #pragma unroll
        for (int q = 0; q < 4; q++) cp16(bu + bswz[q], pBhi + ko + q * 16);
        #pragma unroll
        for (int q = 0; q < 4; q++) cp16(bu + 16384 + bswz[q], pBlo + ko + q * 16);
    };

    // ---- P load (128KB, swizzled) ----
    #pragma unroll
    for (int j = 0; j < 32; j++) {
        int idx = tid + 256 * j;
        int e = idx >> 7, r = idx & 127;           // r: 16B chunk within edge; i = r>>1
        uint32_t d = sbase + OFF_P + (e << 11) + (r << 4);
        d ^= ((((r >> 5) + e) & 7) << 4);          // bank swizzle
        cp16(d, (const char*)g_P + ((size_t)(e0 + e)) * 2048 + (size_t)r * 16);
    }
    CP_COMMIT();                                   // group: P
    loadB(0, 0); CP_COMMIT();                      // group: B0

    // ---- per-thread A-producer mapping ----
    const int ee = tid >> 2;
    const int i0 = (tid & 3) * 16;
    const float* mTe = g_mT + (size_t)(e0 + ee) * 1024;

    float4 mAr[2], mBr[2];
    mAr[0] = *(const float4*)(mTe + 0); mBr[0] = *(const float4*)(mTe + 4);
    loadB(1, 1); CP_COMMIT();                      // group: B1
    mAr[1] = *(const float4*)(mTe + 8); mBr[1] = *(const float4*)(mTe + 12);

    // ---- A producer ----
    auto computeA = [&](int buf, float4 ma, float4 mb) {
        float a[16];
        #pragma unroll
        for (int j = 0; j < 16; j++) {
            int i = i0 + j;
            uint32_t off = OFF_P + (ee << 11) + i * 32;
            off ^= ((((i >> 4) + ee) & 7) << 4);
            float4 p0 = *(const float4*)(smem + off);
            float4 p1 = *(const float4*)(smem + (off ^ 16));
            a[j] = p0.x * ma.x + p0.y * ma.y + p0.z * ma.z + p0.w * ma.w
                 + p1.x * mb.x + p1.y * mb.y + p1.z * mb.z + p1.w * mb.w;
        }
        unsigned hi[8], lo[8];
        #pragma unroll
        for (int q = 0; q < 8; q++) {
            __half h0 = __float2half_rn(a[2*q]), h1 = __float2half_rn(a[2*q+1]);
            hi[q] = pack_hh(h0, h1);
            lo[q] = pack_ff(a[2*q] - __half2float(h0), a[2*q+1] - __half2float(h1));
        }
        const uint32_t c0 = ee * 128 + i0 * 2;
        char* ab = smem + OFF_A + buf * 16384;
        *(uint4*)(ab + SWZ128(c0))          = make_uint4(hi[0], hi[1], hi[2], hi[3]);
        *(uint4*)(ab + SWZ128(c0 + 16))     = make_uint4(hi[4], hi[5], hi[6], hi[7]);
        *(uint4*)(ab + 8192 + SWZ128(c0))      = make_uint4(lo[0], lo[1], lo[2], lo[3]);
        *(uint4*)(ab + 8192 + SWZ128(c0 + 16)) = make_uint4(lo[4], lo[5], lo[6], lo[7]);
    };

    // ---- ldmatrix offsets ----
    uint32_t aoff[2];
    #pragma unroll
    for (int mt = 0; mt < 2; mt++)
        aoff[mt] = (warp_m * 32 + mt * 16 + (lane & 15)) * 128 + (lane >> 4) * 16;
    uint32_t boff[2];
    #pragma unroll
    for (int p = 0; p < 2; p++) {
        int g = lane >> 3;
        int n = warp_n * 32 + (2 * p + (g >> 1)) * 8 + (lane & 7);
        boff[p] = n * 128 + (g & 1) * 16;
    }

    float acc[2][4][4];
    #pragma unroll
    for (int mt = 0; mt < 2; mt++)
        #pragma unroll
        for (int nt = 0; nt < 4; nt++)
            #pragma unroll
            for (int q = 0; q < 4; q++) acc[mt][nt][q] = 0.f;

    // ---- prologue: P arrived -> A(0); then B0 visible ----
    CP_WAIT(2);            // P done (B0,B1 still pending)
    __syncthreads();
    computeA(0, mAr[0], mBr[0]);
    CP_WAIT(1);            // B0 done
    __syncthreads();       // A(0) + B(0) visible to all

    // ---- main loop ----
    #pragma unroll 2
    for (int t = 0; t < NT; t++) {
        const int buf = t & 1;
        const uint32_t au = sbase + OFF_A + buf * 16384;
        const uint32_t bu = sbase + OFF_B + buf * 32768;

        #pragma unroll
        for (int ks = 0; ks < 4; ks++) {
            const int kb = ks * 32;
            uint32_t ah[2][4], al[2][4], bh[4][2], bl[4][2];
            #pragma unroll
            for (int mt = 0; mt < 2; mt++) {
                ldmx4(ah[mt], au + SWZ128(aoff[mt] + kb));
                ldmx4(al[mt], au + 8192 + SWZ128(aoff[mt] + kb));
            }
            #pragma unroll
            for (int p = 0; p < 2; p++) {
                uint32_t b4[4];
                ldmx4(b4, bu + SWZ128(boff[p] + kb));
                bh[2*p][0] = b4[0]; bh[2*p][1] = b4[1];
                bh[2*p+1][0] = b4[2]; bh[2*p+1][1] = b4[3];
                ldmx4(b4, bu + 16384 + SWZ128(boff[p] + kb));
                bl[2*p][0] = b4[0]; bl[2*p][1] = b4[1];
                bl[2*p+1][0] = b4[2]; bl[2*p+1][1] = b4[3];
            }
            #pragma unroll
            for (int mt = 0; mt < 2; mt++)
                #pragma unroll
                for (int nt = 0; nt < 4; nt++) {
                    mma16816(acc[mt][nt], ah[mt], bh[nt]);
                    mma16816(acc[mt][nt], ah[mt], bl[nt]);
                    mma16816(acc[mt][nt], al[mt], bh[nt]);
                }
        }

        if (t + 1 < NT)
            computeA((t + 1) & 1, mAr[(t + 1) & 1], mBr[(t + 1) & 1]);

        CP_WAIT(0);        // B(t+1) landed (issued last iter)
        __syncthreads();   // everyone done with bufs of tile t; A(t+1)/B(t+1) visible

        if (t + 2 < NT) {
            loadB(t + 2, buf);     // overwrite the stage tile t just finished
            CP_COMMIT();
            const float* mp = mTe + (t + 2) * 8;
            mAr[buf] = *(const float4*)mp;
            mBr[buf] = *(const float4*)(mp + 4);
        }
    }

    // ---- epilogue ----
    #pragma unroll
    for (int mt = 0; mt < 2; mt++) {
        const int row0 = e0 + warp_m * 32 + mt * 16 + (lane >> 2);
        #pragma unroll
        for (int nt = 0; nt < 4; nt++) {
            const int col = warp_n * 32 + nt * 8 + (lane & 3) * 2;
            if (row0 < E_EDGES)
                *(float2*)&out[(size_t)row0 * 128 + col] =
                    make_float2(acc[mt][nt][0], acc[mt][nt][1]);
            if (row0 + 8 < E_EDGES)
                *(float2*)&out[(size_t)(row0 + 8) * 128 + col] =
                    make_float2(acc[mt][nt][2], acc[mt][nt][3]);
        }
    }
}

// ---------------------------------------------------------------------------
extern "C" void kernel_launch(void* const* d_in, const int* in_sizes, int n_in,
                              void* d_out, int out_size) {
    const float* rbf = (const float*)d_in[0];   // (E, 64, 16)
    const float* sph = (const float*)d_in[1];   // (E, 16, 16)
    const float* m   = (const float*)d_in[2];   // (E*8, 128)
    const float* w   = (const float*)d_in[3];   // (128, 64, 128)
    float* out = (float*)d_out;

    cudaFuncSetAttribute(gemm_kernel, cudaFuncAttributeMaxDynamicSharedMemorySize, SMEM_TOTAL_GEMM);

    wsplit_kernel<<<128, 256>>>(w);
    prep_kernel<<<EPAD, 256>>>(rbf, sph, m);
    gemm_kernel<<<MTILES, 256, SMEM_TOTAL_GEMM>>>(out);
}